// round 2
// baseline (speedup 1.0000x reference)
#include <cuda_runtime.h>
#include <stdint.h>

#define N_NODES 10242
#define NNZ_MAX 71694
#define BT      32          // B*T
#define C_IN    16
#define F       512         // C_IN * BT
#define KS      20
#define COUT    32
#define NPB     8           // nodes per gemm block

typedef unsigned long long ull;

// ---------------- device scratch (no runtime allocation allowed) ----------------
__device__ float g_xs[(size_t)KS * N_NODES * F];   // all Chebyshev slices, ~420MB
__device__ int   g_rowptr[N_NODES + 1];
__device__ int   g_colidx[NNZ_MAX];
__device__ float g_vals[NNZ_MAX];
__device__ float g_Wt[C_IN * KS * COUT];           // W transposed: [ck][cout]

// ---------------- single-block CSR build (count+scan+scatter+sort) ----------------
__global__ void __launch_bounds__(1024) csr_build_kernel(const int* __restrict__ erow,
                                                         const int* __restrict__ ecol,
                                                         const float* __restrict__ eval,
                                                         int nnz) {
    __shared__ int scnt[N_NODES];     // counts -> cursors
    __shared__ int ssum[1024];
    int t = threadIdx.x;

    for (int i = t; i < N_NODES; i += 1024) scnt[i] = 0;
    __syncthreads();

    for (int e = t; e < nnz; e += 1024) atomicAdd(&scnt[erow[e]], 1);
    __syncthreads();

    const int CH = 11;                 // 1024*11 = 11264 >= 10242
    int base = t * CH;
    int s = 0;
#pragma unroll
    for (int i = 0; i < CH; ++i) {
        int idx = base + i;
        if (idx < N_NODES) s += scnt[idx];
    }
    ssum[t] = s;
    __syncthreads();
    for (int off = 1; off < 1024; off <<= 1) {
        int v = (t >= off) ? ssum[t - off] : 0;
        __syncthreads();
        ssum[t] += v;
        __syncthreads();
    }
    int run = ssum[t] - s;             // exclusive prefix at chunk start
#pragma unroll
    for (int i = 0; i < CH; ++i) {
        int idx = base + i;
        if (idx < N_NODES) {
            int c = scnt[idx];
            g_rowptr[idx] = run;
            scnt[idx] = run;           // becomes cursor
            run += c;
        }
    }
    if (t == 0) g_rowptr[N_NODES] = nnz;
    __syncthreads();

    for (int e = t; e < nnz; e += 1024) {
        int r = erow[e];
        int p = atomicAdd(&scnt[r], 1);
        g_colidx[p] = ecol[e];
        g_vals[p]   = eval[e];
    }
    __syncthreads();

    // canonical per-row order (col asc, then val asc) -> deterministic fp sums
    for (int r = t; r < N_NODES; r += 1024) {
        int rs = g_rowptr[r], re = g_rowptr[r + 1];
        for (int i = rs + 1; i < re; ++i) {
            int   kc = g_colidx[i];
            float kv = g_vals[i];
            int j = i - 1;
            while (j >= rs && (g_colidx[j] > kc || (g_colidx[j] == kc && g_vals[j] > kv))) {
                g_colidx[j + 1] = g_colidx[j];
                g_vals[j + 1]   = g_vals[j];
                --j;
            }
            g_colidx[j + 1] = kc;
            g_vals[j + 1]   = kv;
        }
    }
}

// ---------------- W transpose: g_Wt[ck*COUT + cout] = W[cout*CK + ck] ----------------
__global__ void wt_build_kernel(const float* __restrict__ W) {
    int i = blockIdx.x * blockDim.x + threadIdx.x;
    const int CK = C_IN * KS;
    if (i < COUT * CK) {
        int cout = i / CK;
        int ck   = i % CK;
        g_Wt[ck * COUT + cout] = W[i];
    }
}

// ---------------- x [BT,N,C] -> xs slice 0 [N, c*BT+bt] ----------------
__global__ void transpose_kernel(const float* __restrict__ x) {
    __shared__ float sm[F];
    int n = blockIdx.x;
    for (int t = threadIdx.x; t < F; t += blockDim.x) {
        int bt = t >> 4;          // 0..31
        int c  = t & 15;          // 0..15
        sm[c * BT + bt] = x[((size_t)bt * N_NODES + n) * C_IN + c];
    }
    __syncthreads();
    for (int t = threadIdx.x; t < F; t += blockDim.x)
        g_xs[(size_t)n * F + t] = sm[t];
}

// ---------------- SpMM step: warp-per-node, paired-edge pipeline ----------------
#define FMA4(A, V, U) do { \
    A.x = fmaf(V, U.x, A.x); A.y = fmaf(V, U.y, A.y); \
    A.z = fmaf(V, U.z, A.z); A.w = fmaf(V, U.w, A.w); } while (0)

__global__ void __launch_bounds__(256) spmm_kernel(int kc, int kp, int ko, int first) {
    int gw   = (blockIdx.x * 256 + threadIdx.x) >> 5;   // node = global warp id
    int lane = threadIdx.x & 31;
    if (gw >= N_NODES) return;

    const float4* __restrict__ cur = (const float4*)(g_xs + (size_t)kc * N_NODES * F);
    int s = g_rowptr[gw], e = g_rowptr[gw + 1];

    float4 a0 = make_float4(0.f, 0.f, 0.f, 0.f), a1 = a0, a2 = a0, a3 = a0;

    int i = s;
    for (; i + 2 <= e; i += 2) {
        int   c0 = __ldg(&g_colidx[i]);
        int   c1 = __ldg(&g_colidx[i + 1]);
        float v0 = __ldg(&g_vals[i]);
        float v1 = __ldg(&g_vals[i + 1]);
        const float4* p0 = cur + (size_t)c0 * 128 + lane;
        const float4* p1 = cur + (size_t)c1 * 128 + lane;
        float4 u0 = __ldg(p0),      u1 = __ldg(p0 + 32),
               u2 = __ldg(p0 + 64), u3 = __ldg(p0 + 96);
        float4 w0 = __ldg(p1),      w1 = __ldg(p1 + 32),
               w2 = __ldg(p1 + 64), w3 = __ldg(p1 + 96);
        FMA4(a0, v0, u0); FMA4(a1, v0, u1); FMA4(a2, v0, u2); FMA4(a3, v0, u3);
        FMA4(a0, v1, w0); FMA4(a1, v1, w1); FMA4(a2, v1, w2); FMA4(a3, v1, w3);
    }
    if (i < e) {
        int   c0 = __ldg(&g_colidx[i]);
        float v0 = __ldg(&g_vals[i]);
        const float4* p0 = cur + (size_t)c0 * 128 + lane;
        float4 u0 = __ldg(p0),      u1 = __ldg(p0 + 32),
               u2 = __ldg(p0 + 64), u3 = __ldg(p0 + 96);
        FMA4(a0, v0, u0); FMA4(a1, v0, u1); FMA4(a2, v0, u2); FMA4(a3, v0, u3);
    }

    size_t o = (size_t)gw * 128 + lane;
    float4* dst = (float4*)(g_xs + (size_t)ko * N_NODES * F);
    if (first) {
        dst[o] = a0; dst[o + 32] = a1; dst[o + 64] = a2; dst[o + 96] = a3;
    } else {
        const float4* __restrict__ prev = (const float4*)(g_xs + (size_t)kp * N_NODES * F);
        float4 p0 = prev[o], p1 = prev[o + 32], p2 = prev[o + 64], p3 = prev[o + 96];
        dst[o]      = make_float4(2.f * a0.x - p0.x, 2.f * a0.y - p0.y, 2.f * a0.z - p0.z, 2.f * a0.w - p0.w);
        dst[o + 32] = make_float4(2.f * a1.x - p1.x, 2.f * a1.y - p1.y, 2.f * a1.z - p1.z, 2.f * a1.w - p1.w);
        dst[o + 64] = make_float4(2.f * a2.x - p2.x, 2.f * a2.y - p2.y, 2.f * a2.z - p2.z, 2.f * a2.w - p2.w);
        dst[o + 96] = make_float4(2.f * a3.x - p3.x, 2.f * a3.y - p3.y, 2.f * a3.z - p3.z, 2.f * a3.w - p3.w);
    }
}

// ---------------- final projection: 8 nodes per block, packed f32x2 FFMA ----------------
__device__ __forceinline__ void ffma2(ull& d, ull a, ull b) {
    asm("fma.rn.f32x2 %0, %1, %2, %0;" : "+l"(d) : "l"(a), "l"(b));
}

__global__ void __launch_bounds__(256) gemm_kernel(float* __restrict__ out) {
    extern __shared__ float sh[];
    float* wsm = sh;                     // CK*COUT = 10240 floats (40KB)
    float* sx  = sh + C_IN * KS * COUT;  // KS*F    = 10240 floats (40KB)
    int tid = threadIdx.x;

    // stage W once per block
    for (int i = tid; i < (C_IN * KS * COUT) / 4; i += 256)
        ((float4*)wsm)[i] = ((const float4*)g_Wt)[i];

    int btp = tid >> 4;      // 0..15 -> bt {2btp, 2btp+1}
    int cp  = tid & 15;      // 0..15 -> cout {2cp, 2cp+1}
    int node0 = blockIdx.x * NPB;

    for (int g = 0; g < NPB; ++g) {
        int n = node0 + g;
        if (n >= N_NODES) break;         // uniform across block
        __syncthreads();                 // protect sx reuse (also orders W stage on g==0)
        for (int i = tid; i < (KS * F) / 4; i += 256) {
            int k = i >> 7;              // 128 float4 per slice
            int j = i & 127;
            ((float4*)sx)[i] =
                ((const float4*)(g_xs + (size_t)k * N_NODES * F + (size_t)n * F))[j];
        }
        __syncthreads();

        ull A0 = 0ull, A1 = 0ull;        // A0: bt0 x {c0,c1}; A1: bt1 x {c0,c1}
        for (int k = 0; k < KS; ++k) {
#pragma unroll
            for (int c = 0; c < C_IN; ++c) {
                float2 sv = *(const float2*)&sx[k * F + c * BT + btp * 2];
                ull w2 = *(const ull*)&wsm[(c * KS + k) * COUT + cp * 2];
                ull s0, s1;
                asm("mov.b64 %0, {%1, %1};" : "=l"(s0) : "f"(sv.x));
                asm("mov.b64 %0, {%1, %1};" : "=l"(s1) : "f"(sv.y));
                ffma2(A0, s0, w2);
                ffma2(A1, s1, w2);
            }
        }

        float a00, a01, a10, a11;
        asm("mov.b64 {%0, %1}, %2;" : "=f"(a00), "=f"(a01) : "l"(A0));
        asm("mov.b64 {%0, %1}, %2;" : "=f"(a10), "=f"(a11) : "l"(A1));

        int bt0 = btp * 2, c0 = cp * 2;
        size_t o0 = ((size_t)bt0 * N_NODES + n) * COUT + c0;
        size_t o1 = o0 + (size_t)N_NODES * COUT;
        *(float2*)&out[o0] = make_float2(a00, a01);
        *(float2*)&out[o1] = make_float2(a10, a11);
    }
}

// ---------------- launch ----------------
extern "C" void kernel_launch(void* const* d_in, const int* in_sizes, int n_in,
                              void* d_out, int out_size) {
    const float* x    = (const float*)d_in[0];
    const int*   erow = (const int*)  d_in[1];
    const int*   ecol = (const int*)  d_in[2];
    const float* eval = (const float*)d_in[3];
    const float* W    = (const float*)d_in[4];
    float*       out  = (float*)d_out;
    int nnz = in_sizes[1];
    if (nnz > NNZ_MAX) nnz = NNZ_MAX;

    const int SMEM = 2 * KS * F * (int)sizeof(float);   // 81920 B
    cudaFuncSetAttribute(gemm_kernel, cudaFuncAttributeMaxDynamicSharedMemorySize, SMEM);

    csr_build_kernel<<<1, 1024>>>(erow, ecol, eval, nnz);
    wt_build_kernel <<<(COUT * C_IN * KS + 255) / 256, 256>>>(W);
    transpose_kernel<<<N_NODES, 256>>>(x);              // slice 0

    const int SPMM_BLOCKS = (N_NODES * 32 + 255) / 256; // warp-per-node
    spmm_kernel<<<SPMM_BLOCKS, 256>>>(0, 0, 1, 1);      // slice 1 = L x0
    for (int k = 2; k < KS; ++k)
        spmm_kernel<<<SPMM_BLOCKS, 256>>>(k - 1, k - 2, k, 0);

    gemm_kernel<<<(N_NODES + NPB - 1) / NPB, 256, SMEM>>>(out);
}

// round 3
// speedup vs baseline: 1.1852x; 1.1852x over previous
#include <cuda_runtime.h>
#include <stdint.h>

#define N_NODES 10242
#define NNZ_MAX 71694
#define BT      32          // B*T
#define C_IN    16
#define F       512         // C_IN * BT
#define KS      20
#define COUT    32

typedef unsigned long long ull;

// ---------------- device scratch (no runtime allocation allowed) ----------------
__device__ float g_xs[(size_t)KS * N_NODES * F];   // all Chebyshev slices, ~420MB
__device__ int   g_cnt[N_NODES];
__device__ int   g_rowptr[N_NODES + 1];
__device__ int   g_cursor[N_NODES];
__device__ int   g_colidx[NNZ_MAX];
__device__ float g_vals[NNZ_MAX];
__device__ float g_Wt2[C_IN * KS * COUT * 2];      // W transposed + duplicated: [ck][cout*2]

// ---------------- CSR build (parallel, multi-kernel) ----------------
__global__ void zero_cnt_kernel() {
    int i = blockIdx.x * blockDim.x + threadIdx.x;
    if (i < N_NODES) g_cnt[i] = 0;
}

__global__ void csr_count_kernel(const int* __restrict__ erow, int nnz) {
    int e = blockIdx.x * blockDim.x + threadIdx.x;
    if (e < nnz) atomicAdd(&g_cnt[erow[e]], 1);
}

__global__ void csr_scan_kernel(int nnz) {
    __shared__ int sm[1024];
    int t = threadIdx.x;
    const int CH = 11;                       // 1024*11 = 11264 >= 10242
    int base = t * CH;
    int s = 0;
#pragma unroll
    for (int i = 0; i < CH; ++i) {
        int idx = base + i;
        if (idx < N_NODES) s += g_cnt[idx];
    }
    sm[t] = s;
    __syncthreads();
    for (int off = 1; off < 1024; off <<= 1) {
        int v = (t >= off) ? sm[t - off] : 0;
        __syncthreads();
        sm[t] += v;
        __syncthreads();
    }
    int run = sm[t] - s;                     // exclusive prefix at chunk start
#pragma unroll
    for (int i = 0; i < CH; ++i) {
        int idx = base + i;
        if (idx < N_NODES) {
            g_rowptr[idx] = run;
            g_cursor[idx] = run;
            run += g_cnt[idx];
        }
    }
    if (t == 0) g_rowptr[N_NODES] = nnz;
}

__global__ void csr_scatter_kernel(const int* __restrict__ erow,
                                   const int* __restrict__ ecol,
                                   const float* __restrict__ eval, int nnz) {
    int e = blockIdx.x * blockDim.x + threadIdx.x;
    if (e < nnz) {
        int r = erow[e];
        int p = atomicAdd(&g_cursor[r], 1);
        g_colidx[p] = ecol[e];
        g_vals[p]   = eval[e];
    }
}

// Canonical per-row order (col asc, then val asc) -> deterministic fp sums
__global__ void csr_sort_kernel() {
    int r = blockIdx.x * blockDim.x + threadIdx.x;
    if (r >= N_NODES) return;
    int s = g_rowptr[r], e = g_rowptr[r + 1];
    for (int i = s + 1; i < e; ++i) {
        int   kc = g_colidx[i];
        float kv = g_vals[i];
        int j = i - 1;
        while (j >= s && (g_colidx[j] > kc || (g_colidx[j] == kc && g_vals[j] > kv))) {
            g_colidx[j + 1] = g_colidx[j];
            g_vals[j + 1]   = g_vals[j];
            --j;
        }
        g_colidx[j + 1] = kc;
        g_vals[j + 1]   = kv;
    }
}

// ---------------- W transpose + duplicate: g_Wt2[ck*64 + cout*2 (+1)] = W[cout*CK+ck] ----------------
__global__ void wt_build_kernel(const float* __restrict__ W) {
    int i = blockIdx.x * blockDim.x + threadIdx.x;
    const int CK = C_IN * KS;
    if (i < COUT * CK) {
        int cout = i / CK;
        int ck   = i % CK;
        float v  = W[i];
        g_Wt2[ck * (COUT * 2) + cout * 2]     = v;
        g_Wt2[ck * (COUT * 2) + cout * 2 + 1] = v;
    }
}

// ---------------- x [BT,N,C] -> xs slice 0 [N, c*BT+bt] ----------------
__global__ void transpose_kernel(const float* __restrict__ x) {
    __shared__ float sm[F];
    int n = blockIdx.x;
    for (int t = threadIdx.x; t < F; t += blockDim.x) {
        int bt = t >> 4;          // 0..31
        int c  = t & 15;          // 0..15
        sm[c * BT + bt] = x[((size_t)bt * N_NODES + n) * C_IN + c];
    }
    __syncthreads();
    for (int t = threadIdx.x; t < F; t += blockDim.x)
        g_xs[(size_t)n * F + t] = sm[t];
}

// ---------------- SpMM step: warp-per-node, paired-edge pipeline (at L2 cap) ----------------
#define FMA4(A, V, U) do { \
    A.x = fmaf(V, U.x, A.x); A.y = fmaf(V, U.y, A.y); \
    A.z = fmaf(V, U.z, A.z); A.w = fmaf(V, U.w, A.w); } while (0)

__global__ void __launch_bounds__(256) spmm_kernel(int kc, int kp, int ko, int first) {
    int gw   = (blockIdx.x * 256 + threadIdx.x) >> 5;   // node = global warp id
    int lane = threadIdx.x & 31;
    if (gw >= N_NODES) return;

    const float4* __restrict__ cur = (const float4*)(g_xs + (size_t)kc * N_NODES * F);
    int s = g_rowptr[gw], e = g_rowptr[gw + 1];

    float4 a0 = make_float4(0.f, 0.f, 0.f, 0.f), a1 = a0, a2 = a0, a3 = a0;

    int i = s;
    for (; i + 2 <= e; i += 2) {
        int   c0 = __ldg(&g_colidx[i]);
        int   c1 = __ldg(&g_colidx[i + 1]);
        float v0 = __ldg(&g_vals[i]);
        float v1 = __ldg(&g_vals[i + 1]);
        const float4* p0 = cur + (size_t)c0 * 128 + lane;
        const float4* p1 = cur + (size_t)c1 * 128 + lane;
        float4 u0 = __ldg(p0),      u1 = __ldg(p0 + 32),
               u2 = __ldg(p0 + 64), u3 = __ldg(p0 + 96);
        float4 w0 = __ldg(p1),      w1 = __ldg(p1 + 32),
               w2 = __ldg(p1 + 64), w3 = __ldg(p1 + 96);
        FMA4(a0, v0, u0); FMA4(a1, v0, u1); FMA4(a2, v0, u2); FMA4(a3, v0, u3);
        FMA4(a0, v1, w0); FMA4(a1, v1, w1); FMA4(a2, v1, w2); FMA4(a3, v1, w3);
    }
    if (i < e) {
        int   c0 = __ldg(&g_colidx[i]);
        float v0 = __ldg(&g_vals[i]);
        const float4* p0 = cur + (size_t)c0 * 128 + lane;
        float4 u0 = __ldg(p0),      u1 = __ldg(p0 + 32),
               u2 = __ldg(p0 + 64), u3 = __ldg(p0 + 96);
        FMA4(a0, v0, u0); FMA4(a1, v0, u1); FMA4(a2, v0, u2); FMA4(a3, v0, u3);
    }

    size_t o = (size_t)gw * 128 + lane;
    float4* dst = (float4*)(g_xs + (size_t)ko * N_NODES * F);
    if (first) {
        dst[o] = a0; dst[o + 32] = a1; dst[o + 64] = a2; dst[o + 96] = a3;
    } else {
        const float4* __restrict__ prev = (const float4*)(g_xs + (size_t)kp * N_NODES * F);
        float4 p0 = prev[o], p1 = prev[o + 32], p2 = prev[o + 64], p3 = prev[o + 96];
        dst[o]      = make_float4(2.f * a0.x - p0.x, 2.f * a0.y - p0.y, 2.f * a0.z - p0.z, 2.f * a0.w - p0.w);
        dst[o + 32] = make_float4(2.f * a1.x - p1.x, 2.f * a1.y - p1.y, 2.f * a1.z - p1.z, 2.f * a1.w - p1.w);
        dst[o + 64] = make_float4(2.f * a2.x - p2.x, 2.f * a2.y - p2.y, 2.f * a2.z - p2.z, 2.f * a2.w - p2.w);
        dst[o + 96] = make_float4(2.f * a3.x - p3.x, 2.f * a3.y - p3.y, 2.f * a3.z - p3.z, 2.f * a3.w - p3.w);
    }
}

// ---------------- GEMM: warp-per-node, 8bt x 4cout per thread, packed f32x2 ----------------
__device__ __forceinline__ void ffma2(ull& d, ull a, ull b) {
    asm("fma.rn.f32x2 %0, %1, %2, %0;" : "+l"(d) : "l"(a), "l"(b));
}

#define WSM_FLOATS (C_IN * KS * COUT * 2)   // 20480 floats = 80KB

__global__ void __launch_bounds__(256) gemm_kernel(float* __restrict__ out) {
    extern __shared__ float wsm[];          // pre-duplicated W: [ck][64]
    int tid = threadIdx.x;
    for (int i = tid; i < WSM_FLOATS / 4; i += 256)
        ((float4*)wsm)[i] = ((const float4*)g_Wt2)[i];
    __syncthreads();

    int wid  = tid >> 5;
    int lane = tid & 31;
    int n = blockIdx.x * 8 + wid;
    if (n >= N_NODES) return;               // warp-uniform; no syncs after this

    int bt0 = (lane >> 3) * 8;              // 4 groups of 8 bt
    int cg  = lane & 7;                     // 8 groups of 4 cout

    const float* xbase = g_xs + (size_t)n * F + bt0;
    const float* wbase = wsm + cg * 8;

    ull acc[4][4];
#pragma unroll
    for (int p = 0; p < 4; ++p)
#pragma unroll
        for (int j = 0; j < 4; ++j) acc[p][j] = 0ull;

    for (int k = 0; k < KS; ++k) {
        const float* xk = xbase + (size_t)k * N_NODES * F;
        const float* wk = wbase + k * (COUT * 2);
#pragma unroll 2
        for (int c = 0; c < C_IN; ++c) {
            float4 sa = __ldg((const float4*)(xk + c * BT));
            float4 sb = __ldg((const float4*)(xk + c * BT + 4));
            const float4* wp = (const float4*)(wk + c * (KS * COUT * 2));
            float4 wa = wp[0];
            float4 wb = wp[1];
            ull s0 = ((ull*)&sa)[0], s1 = ((ull*)&sa)[1];
            ull s2 = ((ull*)&sb)[0], s3 = ((ull*)&sb)[1];
            ull w0 = ((ull*)&wa)[0], w1 = ((ull*)&wa)[1];
            ull w2 = ((ull*)&wb)[0], w3 = ((ull*)&wb)[1];
            ffma2(acc[0][0], s0, w0); ffma2(acc[0][1], s0, w1);
            ffma2(acc[0][2], s0, w2); ffma2(acc[0][3], s0, w3);
            ffma2(acc[1][0], s1, w0); ffma2(acc[1][1], s1, w1);
            ffma2(acc[1][2], s1, w2); ffma2(acc[1][3], s1, w3);
            ffma2(acc[2][0], s2, w0); ffma2(acc[2][1], s2, w1);
            ffma2(acc[2][2], s2, w2); ffma2(acc[2][3], s2, w3);
            ffma2(acc[3][0], s3, w0); ffma2(acc[3][1], s3, w1);
            ffma2(acc[3][2], s3, w2); ffma2(acc[3][3], s3, w3);
        }
    }

    // unpack + store: acc[p][j] = { out[bt0+2p][cout0+j], out[bt0+2p+1][cout0+j] }
#pragma unroll
    for (int p = 0; p < 4; ++p) {
        float lo[4], hi[4];
#pragma unroll
        for (int j = 0; j < 4; ++j) {
            float2 v;
            asm("mov.b64 {%0, %1}, %2;" : "=f"(v.x), "=f"(v.y) : "l"(acc[p][j]));
            lo[j] = v.x; hi[j] = v.y;
        }
        size_t o0 = ((size_t)(bt0 + 2 * p)     * N_NODES + n) * COUT + cg * 4;
        size_t o1 = ((size_t)(bt0 + 2 * p + 1) * N_NODES + n) * COUT + cg * 4;
        *(float4*)&out[o0] = make_float4(lo[0], lo[1], lo[2], lo[3]);
        *(float4*)&out[o1] = make_float4(hi[0], hi[1], hi[2], hi[3]);
    }
}

// ---------------- launch ----------------
extern "C" void kernel_launch(void* const* d_in, const int* in_sizes, int n_in,
                              void* d_out, int out_size) {
    const float* x    = (const float*)d_in[0];
    const int*   erow = (const int*)  d_in[1];
    const int*   ecol = (const int*)  d_in[2];
    const float* eval = (const float*)d_in[3];
    const float* W    = (const float*)d_in[4];
    float*       out  = (float*)d_out;
    int nnz = in_sizes[1];
    if (nnz > NNZ_MAX) nnz = NNZ_MAX;

    const int SMEM = WSM_FLOATS * (int)sizeof(float);   // 81920 B
    cudaFuncSetAttribute(gemm_kernel, cudaFuncAttributeMaxDynamicSharedMemorySize, SMEM);

    zero_cnt_kernel   <<<(N_NODES + 255) / 256, 256>>>();
    csr_count_kernel  <<<(nnz + 255) / 256, 256>>>(erow, nnz);
    csr_scan_kernel   <<<1, 1024>>>(nnz);
    csr_scatter_kernel<<<(nnz + 255) / 256, 256>>>(erow, ecol, eval, nnz);
    csr_sort_kernel   <<<(N_NODES + 127) / 128, 128>>>();
    wt_build_kernel   <<<(COUT * C_IN * KS + 255) / 256, 256>>>(W);

    transpose_kernel  <<<N_NODES, 256>>>(x);            // slice 0

    const int SPMM_BLOCKS = (N_NODES * 32 + 255) / 256; // warp-per-node
    spmm_kernel<<<SPMM_BLOCKS, 256>>>(0, 0, 1, 1);      // slice 1 = L x0
    for (int k = 2; k < KS; ++k)
        spmm_kernel<<<SPMM_BLOCKS, 256>>>(k - 1, k - 2, k, 0);

    gemm_kernel<<<(N_NODES + 7) / 8, 256, SMEM>>>(out);
}

// round 4
// speedup vs baseline: 1.1928x; 1.0064x over previous
#include <cuda_runtime.h>
#include <stdint.h>

#define N_NODES 10242
#define NNZ_MAX 71694
#define BT      32          // B*T
#define C_IN    16
#define F       512         // C_IN * BT
#define KS      20
#define COUT    32

typedef unsigned long long ull;

// ---------------- device scratch (no runtime allocation allowed) ----------------
__device__ float g_xs[(size_t)KS * N_NODES * F];   // all Chebyshev slices, ~420MB
__device__ int   g_cnt[N_NODES];
__device__ int   g_rowptr[N_NODES + 1];
__device__ int   g_cursor[N_NODES];
__device__ int   g_colidx[NNZ_MAX];
__device__ float g_vals[NNZ_MAX];
__device__ float g_Wt2[C_IN * KS * COUT * 2];      // W transposed + duplicated: [ck][cout*2]

// ---------------- CSR build (parallel, multi-kernel) ----------------
__global__ void zero_cnt_kernel() {
    int i = blockIdx.x * blockDim.x + threadIdx.x;
    if (i < N_NODES) g_cnt[i] = 0;
}

__global__ void csr_count_kernel(const int* __restrict__ erow, int nnz) {
    int e = blockIdx.x * blockDim.x + threadIdx.x;
    if (e < nnz) atomicAdd(&g_cnt[erow[e]], 1);
}

__global__ void csr_scan_kernel(int nnz) {
    __shared__ int sm[1024];
    int t = threadIdx.x;
    const int CH = 11;                       // 1024*11 = 11264 >= 10242
    int base = t * CH;
    int s = 0;
#pragma unroll
    for (int i = 0; i < CH; ++i) {
        int idx = base + i;
        if (idx < N_NODES) s += g_cnt[idx];
    }
    sm[t] = s;
    __syncthreads();
    for (int off = 1; off < 1024; off <<= 1) {
        int v = (t >= off) ? sm[t - off] : 0;
        __syncthreads();
        sm[t] += v;
        __syncthreads();
    }
    int run = sm[t] - s;                     // exclusive prefix at chunk start
#pragma unroll
    for (int i = 0; i < CH; ++i) {
        int idx = base + i;
        if (idx < N_NODES) {
            g_rowptr[idx] = run;
            g_cursor[idx] = run;
            run += g_cnt[idx];
        }
    }
    if (t == 0) g_rowptr[N_NODES] = nnz;
}

__global__ void csr_scatter_kernel(const int* __restrict__ erow,
                                   const int* __restrict__ ecol,
                                   const float* __restrict__ eval, int nnz) {
    int e = blockIdx.x * blockDim.x + threadIdx.x;
    if (e < nnz) {
        int r = erow[e];
        int p = atomicAdd(&g_cursor[r], 1);
        g_colidx[p] = ecol[e];
        g_vals[p]   = eval[e];
    }
}

// Canonical per-row order (col asc, then val asc) -> deterministic fp sums
__global__ void csr_sort_kernel() {
    int r = blockIdx.x * blockDim.x + threadIdx.x;
    if (r >= N_NODES) return;
    int s = g_rowptr[r], e = g_rowptr[r + 1];
    for (int i = s + 1; i < e; ++i) {
        int   kc = g_colidx[i];
        float kv = g_vals[i];
        int j = i - 1;
        while (j >= s && (g_colidx[j] > kc || (g_colidx[j] == kc && g_vals[j] > kv))) {
            g_colidx[j + 1] = g_colidx[j];
            g_vals[j + 1]   = g_vals[j];
            --j;
        }
        g_colidx[j + 1] = kc;
        g_vals[j + 1]   = kv;
    }
}

// ---------------- W transpose + duplicate: g_Wt2[ck*64 + cout*2 (+1)] = W[cout*CK+ck] ----------------
__global__ void wt_build_kernel(const float* __restrict__ W) {
    int i = blockIdx.x * blockDim.x + threadIdx.x;
    const int CK = C_IN * KS;
    if (i < COUT * CK) {
        int cout = i / CK;
        int ck   = i % CK;
        float v  = W[i];
        g_Wt2[ck * (COUT * 2) + cout * 2]     = v;
        g_Wt2[ck * (COUT * 2) + cout * 2 + 1] = v;
    }
}

// ---------------- x [BT,N,C] -> xs slice 0 [N, c*BT+bt] ----------------
__global__ void transpose_kernel(const float* __restrict__ x) {
    __shared__ float sm[F];
    int n = blockIdx.x;
    for (int t = threadIdx.x; t < F; t += blockDim.x) {
        int bt = t >> 4;          // 0..31
        int c  = t & 15;          // 0..15
        sm[c * BT + bt] = x[((size_t)bt * N_NODES + n) * C_IN + c];
    }
    __syncthreads();
    for (int t = threadIdx.x; t < F; t += blockDim.x)
        g_xs[(size_t)n * F + t] = sm[t];
}

// ---------------- SpMM step: warp-per-node, paired-edge pipeline (at L2 cap) ----------------
#define FMA4(A, V, U) do { \
    A.x = fmaf(V, U.x, A.x); A.y = fmaf(V, U.y, A.y); \
    A.z = fmaf(V, U.z, A.z); A.w = fmaf(V, U.w, A.w); } while (0)

__global__ void __launch_bounds__(256) spmm_kernel(int kc, int kp, int ko, int first) {
    int gw   = (blockIdx.x * 256 + threadIdx.x) >> 5;   // node = global warp id
    int lane = threadIdx.x & 31;
    if (gw >= N_NODES) return;

    const float4* __restrict__ cur = (const float4*)(g_xs + (size_t)kc * N_NODES * F);
    int s = g_rowptr[gw], e = g_rowptr[gw + 1];

    float4 a0 = make_float4(0.f, 0.f, 0.f, 0.f), a1 = a0, a2 = a0, a3 = a0;

    int i = s;
    for (; i + 2 <= e; i += 2) {
        int   c0 = __ldg(&g_colidx[i]);
        int   c1 = __ldg(&g_colidx[i + 1]);
        float v0 = __ldg(&g_vals[i]);
        float v1 = __ldg(&g_vals[i + 1]);
        const float4* p0 = cur + (size_t)c0 * 128 + lane;
        const float4* p1 = cur + (size_t)c1 * 128 + lane;
        float4 u0 = __ldg(p0),      u1 = __ldg(p0 + 32),
               u2 = __ldg(p0 + 64), u3 = __ldg(p0 + 96);
        float4 w0 = __ldg(p1),      w1 = __ldg(p1 + 32),
               w2 = __ldg(p1 + 64), w3 = __ldg(p1 + 96);
        FMA4(a0, v0, u0); FMA4(a1, v0, u1); FMA4(a2, v0, u2); FMA4(a3, v0, u3);
        FMA4(a0, v1, w0); FMA4(a1, v1, w1); FMA4(a2, v1, w2); FMA4(a3, v1, w3);
    }
    if (i < e) {
        int   c0 = __ldg(&g_colidx[i]);
        float v0 = __ldg(&g_vals[i]);
        const float4* p0 = cur + (size_t)c0 * 128 + lane;
        float4 u0 = __ldg(p0),      u1 = __ldg(p0 + 32),
               u2 = __ldg(p0 + 64), u3 = __ldg(p0 + 96);
        FMA4(a0, v0, u0); FMA4(a1, v0, u1); FMA4(a2, v0, u2); FMA4(a3, v0, u3);
    }

    size_t o = (size_t)gw * 128 + lane;
    float4* dst = (float4*)(g_xs + (size_t)ko * N_NODES * F);
    if (first) {
        dst[o] = a0; dst[o + 32] = a1; dst[o + 64] = a2; dst[o + 96] = a3;
    } else {
        const float4* __restrict__ prev = (const float4*)(g_xs + (size_t)kp * N_NODES * F);
        float4 p0 = prev[o], p1 = prev[o + 32], p2 = prev[o + 64], p3 = prev[o + 96];
        dst[o]      = make_float4(2.f * a0.x - p0.x, 2.f * a0.y - p0.y, 2.f * a0.z - p0.z, 2.f * a0.w - p0.w);
        dst[o + 32] = make_float4(2.f * a1.x - p1.x, 2.f * a1.y - p1.y, 2.f * a1.z - p1.z, 2.f * a1.w - p1.w);
        dst[o + 64] = make_float4(2.f * a2.x - p2.x, 2.f * a2.y - p2.y, 2.f * a2.z - p2.z, 2.f * a2.w - p2.w);
        dst[o + 96] = make_float4(2.f * a3.x - p3.x, 2.f * a3.y - p3.y, 2.f * a3.z - p3.z, 2.f * a3.w - p3.w);
    }
}

// ---------------- GEMM: warp-per-node, 8bt x 4cout/lane, NO smem, W via L1 ----------------
__device__ __forceinline__ void ffma2(ull& d, ull a, ull b) {
    asm("fma.rn.f32x2 %0, %1, %2, %0;" : "+l"(d) : "l"(a), "l"(b));
}

__global__ void __launch_bounds__(128) gemm_kernel(float* __restrict__ out) {
    int gw   = (blockIdx.x * 128 + threadIdx.x) >> 5;   // node = global warp id
    int lane = threadIdx.x & 31;
    if (gw >= N_NODES) return;
    int n = gw;

    int bt0 = (lane >> 3) * 8;              // 4 groups of 8 bt
    int cg  = lane & 7;                     // 8 groups of 4 cout

    const float* xbase = g_xs + (size_t)n * F + bt0;
    const float* wbase = g_Wt2 + cg * 8;    // duplicated pairs for couts cg*4..cg*4+3

    ull acc[4][4];
#pragma unroll
    for (int p = 0; p < 4; ++p)
#pragma unroll
        for (int j = 0; j < 4; ++j) acc[p][j] = 0ull;

    for (int k = 0; k < KS; ++k) {
        const float* xk = xbase + (size_t)k * N_NODES * F;
        const float* wk = wbase + k * (COUT * 2);
#pragma unroll 4
        for (int c = 0; c < C_IN; ++c) {
            float4 sa = __ldg((const float4*)(xk + c * BT));
            float4 sb = __ldg((const float4*)(xk + c * BT + 4));
            float4 wa = __ldg((const float4*)(wk + c * (KS * COUT * 2)));
            float4 wb = __ldg((const float4*)(wk + c * (KS * COUT * 2) + 4));
            ull s0 = ((ull*)&sa)[0], s1 = ((ull*)&sa)[1];
            ull s2 = ((ull*)&sb)[0], s3 = ((ull*)&sb)[1];
            ull w0 = ((ull*)&wa)[0], w1 = ((ull*)&wa)[1];
            ull w2 = ((ull*)&wb)[0], w3 = ((ull*)&wb)[1];
            ffma2(acc[0][0], s0, w0); ffma2(acc[0][1], s0, w1);
            ffma2(acc[0][2], s0, w2); ffma2(acc[0][3], s0, w3);
            ffma2(acc[1][0], s1, w0); ffma2(acc[1][1], s1, w1);
            ffma2(acc[1][2], s1, w2); ffma2(acc[1][3], s1, w3);
            ffma2(acc[2][0], s2, w0); ffma2(acc[2][1], s2, w1);
            ffma2(acc[2][2], s2, w2); ffma2(acc[2][3], s2, w3);
            ffma2(acc[3][0], s3, w0); ffma2(acc[3][1], s3, w1);
            ffma2(acc[3][2], s3, w2); ffma2(acc[3][3], s3, w3);
        }
    }

    // unpack + store: acc[p][j] = { out[bt0+2p][cout0+j], out[bt0+2p+1][cout0+j] }
#pragma unroll
    for (int p = 0; p < 4; ++p) {
        float lo[4], hi[4];
#pragma unroll
        for (int j = 0; j < 4; ++j) {
            float2 v;
            asm("mov.b64 {%0, %1}, %2;" : "=f"(v.x), "=f"(v.y) : "l"(acc[p][j]));
            lo[j] = v.x; hi[j] = v.y;
        }
        size_t o0 = ((size_t)(bt0 + 2 * p)     * N_NODES + n) * COUT + cg * 4;
        size_t o1 = ((size_t)(bt0 + 2 * p + 1) * N_NODES + n) * COUT + cg * 4;
        *(float4*)&out[o0] = make_float4(lo[0], lo[1], lo[2], lo[3]);
        *(float4*)&out[o1] = make_float4(hi[0], hi[1], hi[2], hi[3]);
    }
}

// ---------------- launch ----------------
extern "C" void kernel_launch(void* const* d_in, const int* in_sizes, int n_in,
                              void* d_out, int out_size) {
    const float* x    = (const float*)d_in[0];
    const int*   erow = (const int*)  d_in[1];
    const int*   ecol = (const int*)  d_in[2];
    const float* eval = (const float*)d_in[3];
    const float* W    = (const float*)d_in[4];
    float*       out  = (float*)d_out;
    int nnz = in_sizes[1];
    if (nnz > NNZ_MAX) nnz = NNZ_MAX;

    zero_cnt_kernel   <<<(N_NODES + 255) / 256, 256>>>();
    csr_count_kernel  <<<(nnz + 255) / 256, 256>>>(erow, nnz);
    csr_scan_kernel   <<<1, 1024>>>(nnz);
    csr_scatter_kernel<<<(nnz + 255) / 256, 256>>>(erow, ecol, eval, nnz);
    csr_sort_kernel   <<<(N_NODES + 127) / 128, 128>>>();
    wt_build_kernel   <<<(COUT * C_IN * KS + 255) / 256, 256>>>(W);

    transpose_kernel  <<<N_NODES, 256>>>(x);            // slice 0

    const int SPMM_BLOCKS = (N_NODES * 32 + 255) / 256; // warp-per-node
    spmm_kernel<<<SPMM_BLOCKS, 256>>>(0, 0, 1, 1);      // slice 1 = L x0
    for (int k = 2; k < KS; ++k)
        spmm_kernel<<<SPMM_BLOCKS, 256>>>(k - 1, k - 2, k, 0);

    gemm_kernel<<<(N_NODES * 32 + 127) / 128, 128>>>(out);
}